// round 12
// baseline (speedup 1.0000x reference)
#include <cuda_runtime.h>
#include <cuda_bf16.h>

#define B_     16
#define N_     2048
#define NCTX   2047          // n_ctx = N - NQ
#define NSPLIT 32
#define OFFOUT (16LL*2048*64)

typedef unsigned long long ull;

// scratch: per-batch partial Gram matrices C (96x32) per split, and P^T (32x64)
__device__ float g_C[B_ * NSPLIT * 96 * 32];
__device__ float g_P[B_ * 32 * 64];

__device__ __forceinline__ void ffma2(ull& d, ull a, ull b) {
    asm("fma.rn.f32x2 %0, %1, %2, %0;" : "+l"(d) : "l"(a), "l"(b));
}
__device__ __forceinline__ float hsum2(ull v) {
    return __uint_as_float((unsigned)v) + __uint_as_float((unsigned)(v >> 32));
}
__device__ __forceinline__ ull dup2(float f) {
    unsigned u = __float_as_uint(f);
    return (ull)u | ((ull)u << 32);
}
__device__ __forceinline__ ull pack2(float lo, float hi) {
    ull r;
    asm("mov.b64 %0, {%1, %2};" : "=l"(r) : "f"(lo), "f"(hi));
    return r;
}

// ---------------------------------------------------------------------------
// Kernel A: per (batch, split) partial C = X96[:, kv] @ Q_kv^T   (96 x 32)
// CONFLICT-FREE rebuild:
//   warp w owns q cols 8w..8w+7  -> q loads warp-UNIFORM LDS.64 (broadcast, 1 wf)
//   lane l owns rows l, l+32, l+64 in stride-65 float array
//     -> r loads LDS.32, bank = (65*l + c) mod 32 = l + c : all 32 banks, 1 wf
// Per n-pair: 6 LDS.32 + 8 LDS.64 + 3 mov.b64 + 24 FFMA2. 2-deep prefetch.
// smem: sX [96][65] + sQ [32][66] = 33.4 KB. grid (32, 16) x 128 thr.
// ---------------------------------------------------------------------------
__global__ void __launch_bounds__(128, 4) kA(const float* __restrict__ x) {
    extern __shared__ float sm[];
    float* sX = sm;                    // 96*65 = 6240 words (24960 B)
    float* sQ = sm + 96 * 65;          // 32*66 = 2112 words (8448 B, 8B-aligned)
    const int s = blockIdx.x, b = blockIdx.y;
    const int tid = threadIdx.x;
    const int lane = tid & 31;
    const int w = tid >> 5;            // warp 0..3 -> q cols 8w..8w+7
    const float* xb = x + (size_t)b * 160 * N_;
    const int n0 = s * 64;

    // stage 96x64 tile into sX (stride 65), zero columns n >= NCTX
#pragma unroll
    for (int i = 0; i < 12; i++) {
        const int fi = tid + i * 128;
        const int r = fi >> 4, c4 = fi & 15;
        const int n = n0 + c4 * 4;
        float4 v = *reinterpret_cast<const float4*>(&xb[r * N_ + n]);
        if (n + 4 > NCTX) {
            if (n + 0 >= NCTX) v.x = 0.f;
            if (n + 1 >= NCTX) v.y = 0.f;
            if (n + 2 >= NCTX) v.z = 0.f;
            if (n + 3 >= NCTX) v.w = 0.f;
        }
        float* d = &sX[r * 65 + c4 * 4];
        d[0] = v.x; d[1] = v.y; d[2] = v.z; d[3] = v.w;
    }
    // stage Q copy (rows 0..31) into sQ (stride 66; even offsets -> ull-aligned)
#pragma unroll
    for (int i = 0; i < 4; i++) {
        const int fi = tid + i * 128;
        const int r = fi >> 4, c4 = fi & 15;
        const int n = n0 + c4 * 4;
        float4 v = *reinterpret_cast<const float4*>(&xb[r * N_ + n]);
        if (n + 4 > NCTX) {
            if (n + 0 >= NCTX) v.x = 0.f;
            if (n + 1 >= NCTX) v.y = 0.f;
            if (n + 2 >= NCTX) v.z = 0.f;
            if (n + 3 >= NCTX) v.w = 0.f;
        }
        float* d = &sQ[r * 66 + c4 * 4];
        d[0] = v.x; d[1] = v.y; d[2] = v.z; d[3] = v.w;
    }
    __syncthreads();

    ull acc[3][8];                     // [row k][q j], packed over n-pairs
#pragma unroll
    for (int k = 0; k < 3; k++)
#pragma unroll
        for (int j = 0; j < 8; j++) acc[k][j] = 0ull;

    const int qbase = w * 8;
    const float* qrow = sQ + qbase * 66;

    ull qv[2][8];
    float rl[2][3], rh[2][3];
    // preload slot 0
#pragma unroll
    for (int j = 0; j < 8; j++) qv[0][j] = *reinterpret_cast<const ull*>(qrow + j * 66);
#pragma unroll
    for (int k = 0; k < 3; k++) {
        const int rw = (lane + 32 * k) * 65;
        rl[0][k] = sX[rw]; rh[0][k] = sX[rw + 1];
    }

#pragma unroll 2
    for (int pp = 0; pp < 32; pp++) {
        const int cur = pp & 1, nxt = cur ^ 1;
        if (pp < 31) {
            const int c2 = 2 * (pp + 1);
#pragma unroll
            for (int j = 0; j < 8; j++)
                qv[nxt][j] = *reinterpret_cast<const ull*>(qrow + j * 66 + c2);
#pragma unroll
            for (int k = 0; k < 3; k++) {
                const int rw = (lane + 32 * k) * 65 + c2;
                rl[nxt][k] = sX[rw]; rh[nxt][k] = sX[rw + 1];
            }
        }
#pragma unroll
        for (int k = 0; k < 3; k++) {
            const ull rv = pack2(rl[cur][k], rh[cur][k]);
#pragma unroll
            for (int j = 0; j < 8; j++) ffma2(acc[k][j], rv, qv[cur][j]);
        }
    }

    float* outp = g_C + (size_t)(b * NSPLIT + s) * 3072;
#pragma unroll
    for (int k = 0; k < 3; k++) {
        const int row = lane + 32 * k;
#pragma unroll
        for (int j = 0; j < 8; j++)
            outp[row * 32 + qbase + j] = hsum2(acc[k][j]);
    }
}

// ---------------------------------------------------------------------------
// Kernel B (fused reduce + recursion): 768 thr. Triggers PDL at entry so kC
// can stage its x/Emb tiles concurrently. Reduce: one float4 slot per thread,
// 32 independent strided LDG.128. Recursion on tid<256.
// ---------------------------------------------------------------------------
__global__ void __launch_bounds__(768) kB(const float* __restrict__ alpha,
                                          const float* __restrict__ kpp,
                                          const float* __restrict__ emb,
                                          const float* __restrict__ M) {
#if __CUDA_ARCH__ >= 900
    cudaTriggerProgrammaticLaunchCompletion();
#endif
    __shared__ float sC[3072];
    __shared__ float sS[2048];
    __shared__ float sW[64 * 33];
    __shared__ float sY[2048];
    __shared__ float sWs[2048];
    const int b = blockIdx.x, tid = threadIdx.x;

    {
        const float4* gc = reinterpret_cast<const float4*>(g_C + (size_t)b * (NSPLIT * 3072));
        float4 a = make_float4(0.f, 0.f, 0.f, 0.f);
#pragma unroll 8
        for (int sp = 0; sp < NSPLIT; sp++) {
            const float4 v = gc[sp * 768 + tid];
            a.x += v.x; a.y += v.y; a.z += v.z; a.w += v.w;
        }
        *reinterpret_cast<float4*>(&sC[tid * 4]) = a;
    }
    __syncthreads();

    const bool act = tid < 256;
    const int i = (tid >> 2) & 63;
    const int j0 = (tid & 3) * 8;
    float acc[8];

    if (act) {
#pragma unroll
        for (int u = 0; u < 8; u++) acc[u] = 0.f;
        for (int k = 0; k < 64; k++) {
            const float ev = emb[i * 64 + k];
            const float* row = &sC[(32 + k) * 32 + j0];
#pragma unroll
            for (int u = 0; u < 8; u++) acc[u] += ev * row[u];
        }
#pragma unroll
        for (int u = 0; u < 8; u++) { sS[i * 32 + j0 + u] = acc[u]; sWs[i * 32 + j0 + u] = 0.f; }
    }
    __syncthreads();

    const float c = kpp[0] / (float)NCTX;

    for (int l = 0; l < 3; l++) {
        if (act) {
            const float al = alpha[l * 64 + i];
#pragma unroll
            for (int u = 0; u < 8; u++) {
                const float w = al * sS[i * 32 + j0 + u];
                sW[i * 33 + j0 + u] = w;
                sWs[i * 32 + j0 + u] += w;
            }
        }
        __syncthreads();
        if (act) {
#pragma unroll
            for (int u = 0; u < 8; u++) acc[u] = 0.f;
            for (int k = 0; k < 32; k++) {
                const float wv = sW[i * 33 + k];
                const float* g = &sC[k * 32 + j0];
#pragma unroll
                for (int u = 0; u < 8; u++) acc[u] += wv * g[u];
            }
#pragma unroll
            for (int u = 0; u < 8; u++) sY[i * 32 + j0 + u] = acc[u];
        }
        __syncthreads();
        if (act) {
#pragma unroll
            for (int u = 0; u < 8; u++) acc[u] = 0.f;
            for (int k = 0; k < 64; k++) {
                const float mv = M[i * 64 + k];
                const float* y = &sY[k * 32 + j0];
#pragma unroll
                for (int u = 0; u < 8; u++) acc[u] += mv * y[u];
            }
#pragma unroll
            for (int u = 0; u < 8; u++) sS[i * 32 + j0 + u] += c * acc[u];
        }
        __syncthreads();
    }

    if (act) {
        const int cc = i;
#pragma unroll
        for (int u = 0; u < 8; u++) acc[u] = 0.f;
        for (int d = 0; d < 64; d++) {
            const float ev = emb[d * 64 + cc];
            const float* wr = &sWs[d * 32 + j0];
#pragma unroll
            for (int u = 0; u < 8; u++) acc[u] += ev * wr[u];
        }
#pragma unroll
        for (int u = 0; u < 8; u++)
            g_P[(size_t)b * 2048 + (j0 + u) * 64 + cc] = c * acc[u];
    }
}

// ---------------------------------------------------------------------------
// Kernel C: logits[b,n,:] = R^T h96[:,n], R = [Emb ; P^T] (96x64); softmax.
// PDL: launched while kB runs; stages sV (x) + sR-Emb first (independent),
// then cudaGridDependencySynchronize(), then stages the g_P rows.
// Compute body identical to R11 (conflict-free c-mapping + 2-deep prefetch).
// ---------------------------------------------------------------------------
__global__ void __launch_bounds__(128, 4) kC(const float* __restrict__ x,
                                             const float* __restrict__ emb,
                                             float* __restrict__ out) {
    extern __shared__ float smc[];
    float* sR = smc;                  // [96][64] floats = 24576 B
    float* sV = smc + 96 * 64;        // [96][64] floats = 24576 B
    const int pb = blockIdx.x, b = blockIdx.y;
    const int tid = threadIdx.x;
    const int cg = tid & 7;            // 8 c-groups
    const int ng = tid >> 3;           // 16 n-groups * 4 n
    const int n0 = pb * 64;
    const float* xb = x + (size_t)b * 160 * N_;

    // ---- independent staging (overlaps kB under PDL) ----
    // sR rows 0..63 <- Emb
    {
        const float4* embv = reinterpret_cast<const float4*>(emb);
        float4* sR4 = reinterpret_cast<float4*>(sR);
#pragma unroll
        for (int i = 0; i < 8; i++) {
            const int fi = tid + i * 128;
            sR4[fi] = embv[fi];
        }
    }
    // sV: rows 0..63 <- x rows 96..159 (F), rows 64..95 <- x rows 0..31 (Q)
#pragma unroll
    for (int i = 0; i < 12; i++) {
        const int fi = tid + i * 128;
        const int r = fi >> 4, c4 = fi & 15;
        const int xr = (r < 64) ? (96 + r) : (r - 64);
        const float4 v = *reinterpret_cast<const float4*>(&xb[xr * N_ + n0 + c4 * 4]);
        *reinterpret_cast<float4*>(&sV[r * 64 + c4 * 4]) = v;
    }

    // ---- wait for kB's g_P ----
#if __CUDA_ARCH__ >= 900
    cudaGridDependencySynchronize();
#endif
    // sR rows 64..95 <- P^T
    {
        const float4* gpv = reinterpret_cast<const float4*>(g_P + (size_t)b * 2048);
        float4* sR4 = reinterpret_cast<float4*>(sR);
#pragma unroll
        for (int i = 0; i < 4; i++) {
            const int fi = tid + i * 128;
            sR4[1024 + fi] = gpv[fi];
        }
    }
    __syncthreads();

    ull acc[4][4];       // jp 0,1 -> c = 4cg..+3 ; jp 2,3 -> c = 32+4cg..+3
#pragma unroll
    for (int jp = 0; jp < 4; jp++)
#pragma unroll
        for (int ns = 0; ns < 4; ns++) acc[jp][ns] = 0ull;

    const ulonglong2* sR2 = reinterpret_cast<const ulonglong2*>(sR);  // row = 16 units
    const float4*     sV4 = reinterpret_cast<const float4*>(sV);      // row = 16 units

    ulonglong2 rlo[2], rhi[2];
    float4 vv[2];
    rlo[0] = sR2[cg];          // t = 0
    rhi[0] = sR2[8 + cg];
    vv[0]  = sV4[ng];

#pragma unroll 2
    for (int t = 0; t < 96; t++) {
        const int cur = t & 1, nxt = cur ^ 1;
        if (t < 95) {
            rlo[nxt] = sR2[(t + 1) * 16 + cg];
            rhi[nxt] = sR2[(t + 1) * 16 + 8 + cg];
            vv[nxt]  = sV4[(t + 1) * 16 + ng];
        }
        ull dv[4];
        dv[0] = dup2(vv[cur].x); dv[1] = dup2(vv[cur].y);
        dv[2] = dup2(vv[cur].z); dv[3] = dup2(vv[cur].w);
        const ull rp[4] = { rlo[cur].x, rlo[cur].y, rhi[cur].x, rhi[cur].y };
#pragma unroll
        for (int jp = 0; jp < 4; jp++)
#pragma unroll
            for (int ns = 0; ns < 4; ns++) ffma2(acc[jp][ns], rp[jp], dv[ns]);
    }

    // softmax over 64 c per n (8 local + reduce across 8 cg lanes) + stores
#pragma unroll
    for (int ns = 0; ns < 4; ns++) {
        float vals[8];   // vals[0..3]: c=4cg..+3 ; vals[4..7]: c=32+4cg..+3
#pragma unroll
        for (int jp = 0; jp < 4; jp++) {
            vals[2 * jp]     = __uint_as_float((unsigned)acc[jp][ns]);
            vals[2 * jp + 1] = __uint_as_float((unsigned)(acc[jp][ns] >> 32));
        }
        float m = vals[0];
#pragma unroll
        for (int u = 1; u < 8; u++) m = fmaxf(m, vals[u]);
#pragma unroll
        for (int o = 1; o < 8; o <<= 1) m = fmaxf(m, __shfl_xor_sync(0xffffffffu, m, o));
        float e[8]; float su = 0.f;
#pragma unroll
        for (int u = 0; u < 8; u++) { e[u] = __expf(vals[u] - m); su += e[u]; }
#pragma unroll
        for (int o = 1; o < 8; o <<= 1) su += __shfl_xor_sync(0xffffffffu, su, o);
        const float inv = 1.f / su;

        const int n = n0 + ng * 4 + ns;
        const size_t base = ((size_t)b * N_ + n) * 64;
        *reinterpret_cast<float4*>(&out[base + cg * 4]) =
            make_float4(vals[0], vals[1], vals[2], vals[3]);
        *reinterpret_cast<float4*>(&out[base + 32 + cg * 4]) =
            make_float4(vals[4], vals[5], vals[6], vals[7]);
        *reinterpret_cast<float4*>(&out[OFFOUT + base + cg * 4]) =
            make_float4(e[0] * inv, e[1] * inv, e[2] * inv, e[3] * inv);
        *reinterpret_cast<float4*>(&out[OFFOUT + base + 32 + cg * 4]) =
            make_float4(e[4] * inv, e[5] * inv, e[6] * inv, e[7] * inv);
    }
}

extern "C" void kernel_launch(void* const* d_in, const int* in_sizes, int n_in,
                              void* d_out, int out_size) {
    const float* x     = (const float*)d_in[0];
    const float* alpha = (const float*)d_in[1];
    const float* kp    = (const float*)d_in[2];
    const float* emb   = (const float*)d_in[3];
    const float* M     = (const float*)d_in[4];
    float* out = (float*)d_out;

    const int kaSmem = (96 * 65 + 32 * 66) * 4;   // 33408
    const int kcSmem = 2 * 96 * 64 * 4;           // 49152
    cudaFuncSetAttribute(kA, cudaFuncAttributeMaxDynamicSharedMemorySize, kaSmem);
    cudaFuncSetAttribute(kC, cudaFuncAttributeMaxDynamicSharedMemorySize, kcSmem);

    kA<<<dim3(NSPLIT, B_), 128, kaSmem>>>(x);
    kB<<<B_, 768>>>(alpha, kp, emb, M);

    // kC with programmatic dependent launch: overlaps its x/Emb staging with kB
    cudaLaunchConfig_t cfg = {};
    cfg.gridDim = dim3(N_ / 64, B_);
    cfg.blockDim = dim3(128);
    cfg.dynamicSmemBytes = kcSmem;
    cfg.stream = 0;
    cudaLaunchAttribute at[1];
    at[0].id = cudaLaunchAttributeProgrammaticStreamSerialization;
    at[0].val.programmaticStreamSerializationAllowed = 1;
    cfg.attrs = at;
    cfg.numAttrs = 1;
    cudaLaunchKernelEx(&cfg, kC, x, emb, out);
}

// round 13
// speedup vs baseline: 1.0420x; 1.0420x over previous
#include <cuda_runtime.h>
#include <cuda_bf16.h>

#define B_     16
#define N_     2048
#define NCTX   2047          // n_ctx = N - NQ
#define NSPLIT 32
#define OFFOUT (16LL*2048*64)

typedef unsigned long long ull;

// scratch: per-batch partial Gram matrices C (96x32) per split, and P^T (32x64)
__device__ float g_C[B_ * NSPLIT * 96 * 32];
__device__ float g_P[B_ * 32 * 64];

__device__ __forceinline__ void ffma2(ull& d, ull a, ull b) {
    asm("fma.rn.f32x2 %0, %1, %2, %0;" : "+l"(d) : "l"(a), "l"(b));
}
__device__ __forceinline__ float hsum2(ull v) {
    return __uint_as_float((unsigned)v) + __uint_as_float((unsigned)(v >> 32));
}
__device__ __forceinline__ ull dup2(float f) {
    unsigned u = __float_as_uint(f);
    return (ull)u | ((ull)u << 32);
}
__device__ __forceinline__ ull add2(ull a, ull b) {
    ull r;
    asm("add.rn.f32x2 %0, %1, %2;" : "=l"(r) : "l"(a), "l"(b));
    return r;
}

// ---------------------------------------------------------------------------
// Kernel A (EXACT R11 version — proven 13.66us): per (batch, split) partial
// C = X96[:, kv] @ Q_kv^T (96x32). 64-n tiles, NSPLIT=32, smem 25.3KB,
// grid 512. Thread tile 6r x 4q, FFMA2 over n-pairs, stride-33-ull rows,
// 2-deep register prefetch.
// ---------------------------------------------------------------------------
__global__ void __launch_bounds__(128, 4) kA(const float* __restrict__ x) {
    extern __shared__ float tile[];    // 96*66 floats = 25344 B
    const int s = blockIdx.x, b = blockIdx.y;
    const int tid = threadIdx.x;
    const int rg = tid & 15;           // 16 row groups * 6 rows
    const int qg = tid >> 4;           // 8 q groups * 4 q
    const float* xb = x + (size_t)b * 160 * N_;
    const int n0 = s * 64;

    // stage 96x64 tile (zero column n >= NCTX)
#pragma unroll
    for (int i = 0; i < 12; i++) {
        const int fi = tid + i * 128;
        const int r = fi >> 4, c4 = fi & 15;
        const int n = n0 + c4 * 4;
        float4 v = *reinterpret_cast<const float4*>(&xb[r * N_ + n]);
        if (n + 4 > NCTX) {
            if (n + 0 >= NCTX) v.x = 0.f;
            if (n + 1 >= NCTX) v.y = 0.f;
            if (n + 2 >= NCTX) v.z = 0.f;
            if (n + 3 >= NCTX) v.w = 0.f;
        }
        const int base = r * 66 + c4 * 4;
        tile[base + 0] = v.x; tile[base + 1] = v.y;
        tile[base + 2] = v.z; tile[base + 3] = v.w;
    }
    __syncthreads();

    const ull* tu = reinterpret_cast<const ull*>(tile);  // row stride 33 ull

    ull acc[6][4];
#pragma unroll
    for (int k = 0; k < 6; k++)
#pragma unroll
        for (int j = 0; j < 4; j++) acc[k][j] = 0ull;

    const int rbase = rg * 6;
    const int qbase = qg * 4;

    ull qv[2][4], rv[2][6];
    {
        const int nu = rg & 31;        // pp = 0 slot
#pragma unroll
        for (int j = 0; j < 4; j++) qv[0][j] = tu[(qbase + j) * 33 + nu];
#pragma unroll
        for (int k = 0; k < 6; k++) rv[0][k] = tu[(rbase + k) * 33 + nu];
    }

#pragma unroll 2
    for (int pp = 0; pp < 32; pp++) {
        const int cur = pp & 1, nxt = cur ^ 1;
        if (pp < 31) {
            const int nu = (pp + 1 + rg) & 31;
#pragma unroll
            for (int j = 0; j < 4; j++) qv[nxt][j] = tu[(qbase + j) * 33 + nu];
#pragma unroll
            for (int k = 0; k < 6; k++) rv[nxt][k] = tu[(rbase + k) * 33 + nu];
        }
#pragma unroll
        for (int k = 0; k < 6; k++)
#pragma unroll
            for (int j = 0; j < 4; j++) ffma2(acc[k][j], rv[cur][k], qv[cur][j]);
    }

    float* outp = g_C + (size_t)(b * NSPLIT + s) * 3072;
#pragma unroll
    for (int k = 0; k < 6; k++) {
        float4 o = make_float4(hsum2(acc[k][0]), hsum2(acc[k][1]),
                               hsum2(acc[k][2]), hsum2(acc[k][3]));
        *reinterpret_cast<float4*>(&outp[(rbase + k) * 32 + qbase]) = o;
    }
}

// ---------------------------------------------------------------------------
// Kernel B (fused reduce + recursion): 768 thr. NO explicit PDL trigger —
// PLC fires at block completion, so kC's gridsync correctly waits for g_P
// (R12 triggered at entry: a race). Reduce: one float4 slot per thread,
// 32 independent strided LDG.128. Recursion on tid<256.
// ---------------------------------------------------------------------------
__global__ void __launch_bounds__(768) kB(const float* __restrict__ alpha,
                                          const float* __restrict__ kpp,
                                          const float* __restrict__ emb,
                                          const float* __restrict__ M) {
    __shared__ float sC[3072];
    __shared__ float sS[2048];
    __shared__ float sW[64 * 33];
    __shared__ float sY[2048];
    __shared__ float sWs[2048];
    const int b = blockIdx.x, tid = threadIdx.x;

    {
        const float4* gc = reinterpret_cast<const float4*>(g_C + (size_t)b * (NSPLIT * 3072));
        float4 a = make_float4(0.f, 0.f, 0.f, 0.f);
#pragma unroll 8
        for (int sp = 0; sp < NSPLIT; sp++) {
            const float4 v = gc[sp * 768 + tid];
            a.x += v.x; a.y += v.y; a.z += v.z; a.w += v.w;
        }
        *reinterpret_cast<float4*>(&sC[tid * 4]) = a;
    }
    __syncthreads();

    const bool act = tid < 256;
    const int i = (tid >> 2) & 63;
    const int j0 = (tid & 3) * 8;
    float acc[8];

    if (act) {
#pragma unroll
        for (int u = 0; u < 8; u++) acc[u] = 0.f;
        for (int k = 0; k < 64; k++) {
            const float ev = emb[i * 64 + k];
            const float* row = &sC[(32 + k) * 32 + j0];
#pragma unroll
            for (int u = 0; u < 8; u++) acc[u] += ev * row[u];
        }
#pragma unroll
        for (int u = 0; u < 8; u++) { sS[i * 32 + j0 + u] = acc[u]; sWs[i * 32 + j0 + u] = 0.f; }
    }
    __syncthreads();

    const float c = kpp[0] / (float)NCTX;

    for (int l = 0; l < 3; l++) {
        if (act) {
            const float al = alpha[l * 64 + i];
#pragma unroll
            for (int u = 0; u < 8; u++) {
                const float w = al * sS[i * 32 + j0 + u];
                sW[i * 33 + j0 + u] = w;
                sWs[i * 32 + j0 + u] += w;
            }
        }
        __syncthreads();
        if (act) {
#pragma unroll
            for (int u = 0; u < 8; u++) acc[u] = 0.f;
            for (int k = 0; k < 32; k++) {
                const float wv = sW[i * 33 + k];
                const float* g = &sC[k * 32 + j0];
#pragma unroll
                for (int u = 0; u < 8; u++) acc[u] += wv * g[u];
            }
#pragma unroll
            for (int u = 0; u < 8; u++) sY[i * 32 + j0 + u] = acc[u];
        }
        __syncthreads();
        if (act) {
#pragma unroll
            for (int u = 0; u < 8; u++) acc[u] = 0.f;
            for (int k = 0; k < 64; k++) {
                const float mv = M[i * 64 + k];
                const float* y = &sY[k * 32 + j0];
#pragma unroll
                for (int u = 0; u < 8; u++) acc[u] += mv * y[u];
            }
#pragma unroll
            for (int u = 0; u < 8; u++) sS[i * 32 + j0 + u] += c * acc[u];
        }
        __syncthreads();
    }

    if (act) {
        const int cc = i;
#pragma unroll
        for (int u = 0; u < 8; u++) acc[u] = 0.f;
        for (int d = 0; d < 64; d++) {
            const float ev = emb[d * 64 + cc];
            const float* wr = &sWs[d * 32 + j0];
#pragma unroll
            for (int u = 0; u < 8; u++) acc[u] += ev * wr[u];
        }
#pragma unroll
        for (int u = 0; u < 8; u++)
            g_P[(size_t)b * 2048 + (j0 + u) * 64 + cc] = c * acc[u];
    }
}

// ---------------------------------------------------------------------------
// Kernel C: logits[b,n,:] = R^T h96[:,n], R = [Emb ; P^T] (96x64); softmax.
// NEW: k-split-2, 256 threads: tid<128 accumulates k=0..47, tid>=128 k=48..95
// -> 27.7 warps/SM (2x latency hiding), same instr/crossbar totals.
// Partials combined via smem (sV reused after barrier); lower half does
// softmax + stores. Conflict-free c-mapping + 2-deep prefetch retained.
// PDL: stages x/Emb while kB runs; gridsync before reading g_P.
// ---------------------------------------------------------------------------
__global__ void __launch_bounds__(256) kC(const float* __restrict__ x,
                                          const float* __restrict__ emb,
                                          float* __restrict__ out) {
    extern __shared__ float smc[];
    float* sR = smc;                  // [96][64] floats = 24576 B
    float* sV = smc + 96 * 64;        // [96][64] floats = 24576 B
    const int pb = blockIdx.x, b = blockIdx.y;
    const int tid = threadIdx.x;
    const int cg = tid & 7;            // 8 c-groups
    const int ng = (tid >> 3) & 15;    // 16 n-groups * 4 n
    const int kh = tid >> 7;           // k-half: 0 -> k 0..47, 1 -> k 48..95
    const int n0 = pb * 64;
    const float* xb = x + (size_t)b * 160 * N_;

    // ---- independent staging (overlaps kB under PDL) ----
    // sR rows 0..63 <- Emb
    {
        const float4* embv = reinterpret_cast<const float4*>(emb);
        float4* sR4 = reinterpret_cast<float4*>(sR);
#pragma unroll
        for (int i = 0; i < 4; i++) {
            const int fi = tid + i * 256;
            sR4[fi] = embv[fi];
        }
    }
    // sV: rows 0..63 <- x rows 96..159 (F), rows 64..95 <- x rows 0..31 (Q)
#pragma unroll
    for (int i = 0; i < 6; i++) {
        const int fi = tid + i * 256;
        const int r = fi >> 4, c4 = fi & 15;
        const int xr = (r < 64) ? (96 + r) : (r - 64);
        const float4 v = *reinterpret_cast<const float4*>(&xb[xr * N_ + n0 + c4 * 4]);
        *reinterpret_cast<float4*>(&sV[r * 64 + c4 * 4]) = v;
    }

    // ---- wait for kB's g_P ----
#if __CUDA_ARCH__ >= 900
    cudaGridDependencySynchronize();
#endif
    // sR rows 64..95 <- P^T
    {
        const float4* gpv = reinterpret_cast<const float4*>(g_P + (size_t)b * 2048);
        float4* sR4 = reinterpret_cast<float4*>(sR);
#pragma unroll
        for (int i = 0; i < 2; i++) {
            const int fi = tid + i * 256;
            sR4[1024 + fi] = gpv[fi];
        }
    }
    __syncthreads();

    ull acc[4][4];       // jp 0,1 -> c = 4cg..+3 ; jp 2,3 -> c = 32+4cg..+3
#pragma unroll
    for (int jp = 0; jp < 4; jp++)
#pragma unroll
        for (int ns = 0; ns < 4; ns++) acc[jp][ns] = 0ull;

    const ulonglong2* sR2 = reinterpret_cast<const ulonglong2*>(sR);  // row = 16 units
    const float4*     sV4 = reinterpret_cast<const float4*>(sV);      // row = 16 units
    const int k0 = kh * 48;

    ulonglong2 rlo[2], rhi[2];
    float4 vv[2];
    rlo[0] = sR2[k0 * 16 + cg];
    rhi[0] = sR2[k0 * 16 + 8 + cg];
    vv[0]  = sV4[k0 * 16 + ng];

#pragma unroll 2
    for (int t = 0; t < 48; t++) {
        const int cur = t & 1, nxt = cur ^ 1;
        if (t < 47) {
            const int tn = (k0 + t + 1) * 16;
            rlo[nxt] = sR2[tn + cg];
            rhi[nxt] = sR2[tn + 8 + cg];
            vv[nxt]  = sV4[tn + ng];
        }
        ull dv[4];
        dv[0] = dup2(vv[cur].x); dv[1] = dup2(vv[cur].y);
        dv[2] = dup2(vv[cur].z); dv[3] = dup2(vv[cur].w);
        const ull rp[4] = { rlo[cur].x, rlo[cur].y, rhi[cur].x, rhi[cur].y };
#pragma unroll
        for (int jp = 0; jp < 4; jp++)
#pragma unroll
            for (int ns = 0; ns < 4; ns++) ffma2(acc[jp][ns], rp[jp], dv[ns]);
    }

    // ---- combine k-halves via smem (reuse sV region) ----
    __syncthreads();                       // all sV reads done
    ull* sX = reinterpret_cast<ull*>(sV);  // 128 threads x 17-ull rows = 17408 B
    if (kh == 1) {
        ull* dst = sX + (tid - 128) * 17;
#pragma unroll
        for (int jp = 0; jp < 4; jp++)
#pragma unroll
            for (int ns = 0; ns < 4; ns++) dst[jp * 4 + ns] = acc[jp][ns];
    }
    __syncthreads();
    if (kh == 0) {
        const ull* src = sX + tid * 17;
#pragma unroll
        for (int jp = 0; jp < 4; jp++)
#pragma unroll
            for (int ns = 0; ns < 4; ns++)
                acc[jp][ns] = add2(acc[jp][ns], src[jp * 4 + ns]);

        // softmax over 64 c per n (8 local + reduce across 8 cg lanes) + stores
#pragma unroll
        for (int ns = 0; ns < 4; ns++) {
            float vals[8];   // vals[0..3]: c=4cg..+3 ; vals[4..7]: c=32+4cg..+3
#pragma unroll
            for (int jp = 0; jp < 4; jp++) {
                vals[2 * jp]     = __uint_as_float((unsigned)acc[jp][ns]);
                vals[2 * jp + 1] = __uint_as_float((unsigned)(acc[jp][ns] >> 32));
            }
            float m = vals[0];
#pragma unroll
            for (int u = 1; u < 8; u++) m = fmaxf(m, vals[u]);
#pragma unroll
            for (int o = 1; o < 8; o <<= 1) m = fmaxf(m, __shfl_xor_sync(0xffffffffu, m, o));
            float e[8]; float su = 0.f;
#pragma unroll
            for (int u = 0; u < 8; u++) { e[u] = __expf(vals[u] - m); su += e[u]; }
#pragma unroll
            for (int o = 1; o < 8; o <<= 1) su += __shfl_xor_sync(0xffffffffu, su, o);
            const float inv = 1.f / su;

            const int n = n0 + ng * 4 + ns;
            const size_t base = ((size_t)b * N_ + n) * 64;
            *reinterpret_cast<float4*>(&out[base + cg * 4]) =
                make_float4(vals[0], vals[1], vals[2], vals[3]);
            *reinterpret_cast<float4*>(&out[base + 32 + cg * 4]) =
                make_float4(vals[4], vals[5], vals[6], vals[7]);
            *reinterpret_cast<float4*>(&out[OFFOUT + base + cg * 4]) =
                make_float4(e[0] * inv, e[1] * inv, e[2] * inv, e[3] * inv);
            *reinterpret_cast<float4*>(&out[OFFOUT + base + 32 + cg * 4]) =
                make_float4(e[4] * inv, e[5] * inv, e[6] * inv, e[7] * inv);
        }
    }
}

extern "C" void kernel_launch(void* const* d_in, const int* in_sizes, int n_in,
                              void* d_out, int out_size) {
    const float* x     = (const float*)d_in[0];
    const float* alpha = (const float*)d_in[1];
    const float* kp    = (const float*)d_in[2];
    const float* emb   = (const float*)d_in[3];
    const float* M     = (const float*)d_in[4];
    float* out = (float*)d_out;

    const int kaSmem = 96 * 66 * 4;       // 25344
    const int kcSmem = 2 * 96 * 64 * 4;   // 49152
    cudaFuncSetAttribute(kA, cudaFuncAttributeMaxDynamicSharedMemorySize, kaSmem);
    cudaFuncSetAttribute(kC, cudaFuncAttributeMaxDynamicSharedMemorySize, kcSmem);

    kA<<<dim3(NSPLIT, B_), 128, kaSmem>>>(x);
    kB<<<B_, 768>>>(alpha, kp, emb, M);

    // kC with programmatic dependent launch: overlaps its x/Emb staging with kB.
    // kB has NO early trigger, so gridsync waits for kB completion (g_P safe).
    cudaLaunchConfig_t cfg = {};
    cfg.gridDim = dim3(N_ / 64, B_);
    cfg.blockDim = dim3(256);
    cfg.dynamicSmemBytes = kcSmem;
    cfg.stream = 0;
    cudaLaunchAttribute at[1];
    at[0].id = cudaLaunchAttributeProgrammaticStreamSerialization;
    at[0].val.programmaticStreamSerializationAllowed = 1;
    cfg.attrs = at;
    cfg.numAttrs = 1;
    cudaLaunchKernelEx(&cfg, kC, x, emb, out);
}